// round 3
// baseline (speedup 1.0000x reference)
#include <cuda_runtime.h>
#include <math.h>

#define Bsz 2048
#define Ssz 128
#define HID 256
#define DCc 130
#define TOK 16
#define HSTR 260   // padded H row stride (floats): 260 % 32 == 4 -> conflict-free LDS.128 across rt

// ---------------- device scratch (static, no allocation) ----------------
__device__ float g_Wt[2][HID * HID];      // W1, W2 transposed to K-major [k][o]
__device__ float g_WgT[4][DCc * HID];     // Wg_l transposed [c][o]  (layer 3 uses dout=2 packing)
__device__ float g_WbT[4][DCc * HID];     // Wb_l transposed [c][o]
__device__ float g_cg[4][Bsz * HID];      // cond·Wg[:,2:] + bg + t*Wg[:,1]   per (l, b, o)
__device__ float g_cb[4][Bsz * HID];      // cond·Wb[:,2:]      + t*Wb[:,1]   per (l, b, o)

// ---------------- helpers ----------------
__device__ __forceinline__ float sigm(float x) {
    float e = expf(-fabsf(x));
    float s = 1.0f / (1.0f + e);
    return (x >= 0.0f) ? s : (1.0f - s) * 0.0f + e / (1.0f + e);
}
__device__ __forceinline__ float splus(float x) {
    // numerically stable softplus = max(x,0) + log1p(exp(-|x|))
    return fmaxf(x, 0.0f) + log1pf(expf(-fabsf(x)));
}
__device__ __forceinline__ unsigned long long pk2(float lo, float hi) {
    unsigned long long r;
    asm("mov.b64 %0, {%1, %2};" : "=l"(r) : "f"(lo), "f"(hi));
    return r;
}
__device__ __forceinline__ void up2(unsigned long long v, float& lo, float& hi) {
    asm("mov.b64 {%0, %1}, %2;" : "=f"(lo), "=f"(hi) : "l"(v));
}
__device__ __forceinline__ void fma2(unsigned long long& acc, unsigned long long a, unsigned long long b) {
    asm("fma.rn.f32x2 %0, %1, %2, %0;" : "+l"(acc) : "l"(a), "l"(b));
}
__device__ __forceinline__ float f4e(const float4& v, int i) {
    return (i == 0) ? v.x : (i == 1) ? v.y : (i == 2) ? v.z : v.w;
}

// ---------------- prep: transposes ----------------
struct PrepP { const float* src[10]; };

__global__ void k_prep(PrepP p) {
    int id = blockIdx.y;
    int rows, cols;
    float* dst;
    switch (id) {
        case 0: rows = HID; cols = HID; dst = g_Wt[0]; break;
        case 1: rows = HID; cols = HID; dst = g_Wt[1]; break;
        case 2: rows = HID; cols = DCc; dst = g_WgT[0]; break;
        case 3: rows = HID; cols = DCc; dst = g_WgT[1]; break;
        case 4: rows = HID; cols = DCc; dst = g_WgT[2]; break;
        case 5: rows = 2;   cols = DCc; dst = g_WgT[3]; break;
        case 6: rows = HID; cols = DCc; dst = g_WbT[0]; break;
        case 7: rows = HID; cols = DCc; dst = g_WbT[1]; break;
        case 8: rows = HID; cols = DCc; dst = g_WbT[2]; break;
        default: rows = 2;  cols = DCc; dst = g_WbT[3]; break;
    }
    int idx = blockIdx.x * blockDim.x + threadIdx.x;
    if (idx < rows * cols) {
        int r = idx / cols, c = idx % cols;
        dst[c * rows + r] = p.src[id][idx];
    }
}

// ---------------- ctx: per-(l,b,o) gate / hyper-bias bases ----------------
struct CtxP { const float* t; const float* cond; const float* bg[4]; };

__global__ void k_ctx(CtxP p) {
    __shared__ float sc[16 * 128];
    int l = blockIdx.y;
    int b0 = blockIdx.x * 16;
    int tid = threadIdx.x;
    for (int i = tid; i < 16 * 128; i += 256) sc[i] = p.cond[b0 * 128 + i];
    __syncthreads();

    int dout = (l < 3) ? HID : 2;
    int o = tid;
    if (o < dout) {
        const float* wgT = g_WgT[l];
        const float* wbT = g_WbT[l];
        float ag[16], ab[16];
#pragma unroll
        for (int bb = 0; bb < 16; bb++) { ag[bb] = 0.f; ab[bb] = 0.f; }
        for (int c = 0; c < 128; c++) {
            float wg = wgT[(2 + c) * dout + o];
            float wb = wbT[(2 + c) * dout + o];
#pragma unroll
            for (int bb = 0; bb < 16; bb++) {
                float cv = sc[bb * 128 + c];
                ag[bb] = fmaf(cv, wg, ag[bb]);
                ab[bb] = fmaf(cv, wb, ab[bb]);
            }
        }
        float tv = __ldg(p.t);
        float baseg = __ldg(&p.bg[l][o]) + tv * wgT[1 * dout + o];
        float baseb = tv * wbT[1 * dout + o];
#pragma unroll
        for (int bb = 0; bb < 16; bb++) {
            g_cg[l][(b0 + bb) * HID + o] = ag[bb] + baseg;
            g_cb[l][(b0 + bb) * HID + o] = ab[bb] + baseb;
        }
    }
}

// ---------------- zero-fill for the condition-gradient output ----------------
__global__ void k_zero(float* dst, int n) {
    int idx = blockIdx.x * blockDim.x + threadIdx.x;
    if (idx < n) dst[idx] = 0.0f;
}

// ---------------- main fused kernel ----------------
struct MainP {
    const float* z;
    const float* W0; const float* b0; const float* Wg0; const float* Wb0;
    const float* b1; const float* Wg1; const float* Wb1;
    const float* b2; const float* Wg2; const float* Wb2;
    const float* W3; const float* b3; const float* Wg3; const float* Wb3;
    float* zdot; float* tr;
};

// dynamic smem layout (floats):
//   H    : 3*TOK*HSTR = 12480
//   WS   : 16*HID     = 4096
//   sCg, sCb, sWg0, sWb0, sB : 5*256 = 1280
//   sz(32) spos(16) sTr(32)  = 80
#define SMEM_FLOATS (12480 + 4096 + 1280 + 80)
#define SMEM_BYTES  (SMEM_FLOATS * 4)

__global__ void __launch_bounds__(256, 2) k_main(MainP p) {
    extern __shared__ float sm[];
    float* H    = sm;
    float* WS   = H + 3 * TOK * HSTR;
    float* sCg  = WS + 16 * HID;
    float* sCb  = sCg + 256;
    float* sWg0 = sCb + 256;
    float* sWb0 = sWg0 + 256;
    float* sB   = sWb0 + 256;
    float* sz   = sB + 256;
    float* spos = sz + 32;
    float* sTr  = spos + 16;

    const int tid = threadIdx.x;
    const int b   = blockIdx.y;
    const int s0  = blockIdx.x * TOK;
    const int rt  = tid & 15;   // token row owned by this thread
    const int ct  = tid >> 4;   // column group

    if (tid < 32) sz[tid] = p.z[(b * Ssz + s0) * 2 + tid];
    if (tid < 16) spos[tid] = (float)(s0 + tid + 1) * (1.0f / Ssz);
    __syncthreads();

    // ---- layer 0: din=2 -> 256, thread o = tid over all 16 tokens ----
    {
        int o = tid;
        float w00 = __ldg(&p.W0[o * 2 + 0]);
        float w01 = __ldg(&p.W0[o * 2 + 1]);
        float bb  = __ldg(&p.b0[o]);
        float cg  = g_cg[0][b * HID + o];
        float cb  = g_cb[0][b * HID + o];
        float wg0 = __ldg(&p.Wg0[o * DCc]);
        float wb0 = __ldg(&p.Wb0[o * DCc]);
#pragma unroll
        for (int tk = 0; tk < TOK; tk++) {
            float z0 = sz[2 * tk], z1 = sz[2 * tk + 1], pos = spos[tk];
            float g   = sigm(cg + pos * wg0);
            float lin = fmaf(z0, w00, fmaf(z1, w01, bb));
            float pre = fmaf(lin, g, cb + pos * wb0);
            float sgp = sigm(pre);
            float f   = sgp * g;
            H[(0 * TOK + tk) * HSTR + o] = splus(pre);
            H[(1 * TOK + tk) * HSTR + o] = f * w00;
            H[(2 * TOK + tk) * HSTR + o] = f * w01;
        }
    }

    // ---- mid layers 1, 2: fused GEMM (3 vec x 16 tok x 256) + elementwise ----
    for (int l = 1; l <= 2; l++) {
        const float* bl  = (l == 1) ? p.b1  : p.b2;
        const float* Wgl = (l == 1) ? p.Wg1 : p.Wg2;
        const float* Wbl = (l == 1) ? p.Wb1 : p.Wb2;
        const float* Wt  = g_Wt[l - 1];

        sCg[tid]  = g_cg[l][b * HID + tid];
        sCb[tid]  = g_cb[l][b * HID + tid];
        sWg0[tid] = __ldg(&Wgl[tid * DCc]);
        sWb0[tid] = __ldg(&Wbl[tid * DCc]);
        sB[tid]   = __ldg(&bl[tid]);

        unsigned long long acc[3][4][2];
#pragma unroll
        for (int v = 0; v < 3; v++)
#pragma unroll
            for (int j = 0; j < 4; j++) { acc[v][j][0] = 0ull; acc[v][j][1] = 0ull; }

        for (int kc = 0; kc < HID; kc += 16) {
            __syncthreads();
            {
                const float4* src4 = (const float4*)(Wt + kc * HID);
                float4* WS4 = (float4*)WS;
#pragma unroll
                for (int r = 0; r < 4; r++) WS4[tid + 256 * r] = src4[tid + 256 * r];
            }
            __syncthreads();
#pragma unroll
            for (int q = 0; q < 4; q++) {
                int k = kc + q * 4;
                float4 a0 = *(const float4*)&H[(0 * TOK + rt) * HSTR + k];
                float4 a1 = *(const float4*)&H[(1 * TOK + rt) * HSTR + k];
                float4 a2 = *(const float4*)&H[(2 * TOK + rt) * HSTR + k];
#pragma unroll
                for (int ki = 0; ki < 4; ki++) {
                    float e0 = f4e(a0, ki), e1 = f4e(a1, ki), e2 = f4e(a2, ki);
                    unsigned long long A0 = pk2(e0, e0);
                    unsigned long long A1 = pk2(e1, e1);
                    unsigned long long A2 = pk2(e2, e2);
                    const float* wrow = WS + (q * 4 + ki) * HID + ct * 4;
#pragma unroll
                    for (int j = 0; j < 4; j++) {
                        float4 w = *(const float4*)(wrow + 64 * j);
                        unsigned long long W01 = pk2(w.x, w.y);
                        unsigned long long W23 = pk2(w.z, w.w);
                        fma2(acc[0][j][0], A0, W01); fma2(acc[0][j][1], A0, W23);
                        fma2(acc[1][j][0], A1, W01); fma2(acc[1][j][1], A1, W23);
                        fma2(acc[2][j][0], A2, W01); fma2(acc[2][j][1], A2, W23);
                    }
                }
            }
        }
        __syncthreads();

        // epilogue: gate + softplus + tangent scaling, write back to H
        {
            float pos = spos[rt];
            float fArr[16];
#pragma unroll
            for (int j = 0; j < 4; j++) {
                int c0 = ct * 4 + 64 * j;
                float a[4];
                up2(acc[0][j][0], a[0], a[1]);
                up2(acc[0][j][1], a[2], a[3]);
                float4 hv;
#pragma unroll
                for (int e = 0; e < 4; e++) {
                    int c = c0 + e;
                    float g   = sigm(sCg[c] + pos * sWg0[c]);
                    float pre = fmaf(a[e] + sB[c], g, sCb[c] + pos * sWb0[c]);
                    ((float*)&hv)[e] = splus(pre);
                    fArr[j * 4 + e] = sigm(pre) * g;
                }
                *(float4*)&H[(0 * TOK + rt) * HSTR + c0] = hv;
            }
#pragma unroll
            for (int v = 1; v < 3; v++) {
#pragma unroll
                for (int j = 0; j < 4; j++) {
                    int c0 = ct * 4 + 64 * j;
                    float a[4];
                    up2(acc[v][j][0], a[0], a[1]);
                    up2(acc[v][j][1], a[2], a[3]);
                    float4 dv;
#pragma unroll
                    for (int e = 0; e < 4; e++)
                        ((float*)&dv)[e] = fArr[j * 4 + e] * a[e];
                    *(float4*)&H[(v * TOK + rt) * HSTR + c0] = dv;
                }
            }
        }
        __syncthreads();
    }

    // ---- layer 3: 256 -> 2, only diagonal tangent dots needed ----
    if (tid < 64) {
        int tk = tid >> 2, r = tid & 3;
        int vec = (r < 2) ? 0 : (r - 1);
        int j   = (r < 2) ? r : (r - 2);
        const float* hrow = &H[(vec * TOK + tk) * HSTR];
        const float* w3   = p.W3 + j * HID;
        float accv = 0.0f;
#pragma unroll 8
        for (int k = 0; k < HID; k += 4) {
            float4 hv = *(const float4*)&hrow[k];
            float4 wv = *(const float4*)&w3[k];
            accv += hv.x * wv.x + hv.y * wv.y + hv.z * wv.z + hv.w * wv.w;
        }
        float pos = spos[tk];
        float g3 = sigm(g_cg[3][b * HID + j] + pos * __ldg(&p.Wg3[j * DCc]));
        if (vec == 0) {
            float hb3  = g_cb[3][b * HID + j] + pos * __ldg(&p.Wb3[j * DCc]);
            float outv = fmaf(accv + __ldg(&p.b3[j]), g3, hb3);
            p.zdot[(b * Ssz + s0 + tk) * 2 + j] = outv;
        } else {
            sTr[tk * 2 + j] = g3 * accv;   // vec==1 -> j==0, vec==2 -> j==1 (diagonal)
        }
    }
    __syncthreads();
    if (tid < TOK) p.tr[b * Ssz + s0 + tid] = -(sTr[tid * 2] + sTr[tid * 2 + 1]);
}

// ---------------- launch ----------------
extern "C" void kernel_launch(void* const* d_in, const int* in_sizes, int n_in,
                              void* d_out, int out_size) {
    const float* t    = (const float*)d_in[0];
    const float* z    = (const float*)d_in[1];
    const float* cond = (const float*)d_in[2];
    const float* W0  = (const float*)d_in[3];
    const float* b0  = (const float*)d_in[4];
    const float* Wg0 = (const float*)d_in[5];
    const float* bg0 = (const float*)d_in[6];
    const float* Wb0 = (const float*)d_in[7];
    const float* W1  = (const float*)d_in[8];
    const float* b1  = (const float*)d_in[9];
    const float* Wg1 = (const float*)d_in[10];
    const float* bg1 = (const float*)d_in[11];
    const float* Wb1 = (const float*)d_in[12];
    const float* W2  = (const float*)d_in[13];
    const float* b2  = (const float*)d_in[14];
    const float* Wg2 = (const float*)d_in[15];
    const float* bg2 = (const float*)d_in[16];
    const float* Wb2 = (const float*)d_in[17];
    const float* W3  = (const float*)d_in[18];
    const float* b3  = (const float*)d_in[19];
    const float* Wg3 = (const float*)d_in[20];
    const float* bg3 = (const float*)d_in[21];
    const float* Wb3 = (const float*)d_in[22];

    float* out = (float*)d_out;
    float* zdot    = out;                         // [2048,128,2]
    float* trace   = out + Bsz * Ssz * 2;         // [2048,128]
    float* condg   = out + Bsz * Ssz * 3;         // [2048,128] zeros

    PrepP pp;
    pp.src[0] = W1;  pp.src[1] = W2;
    pp.src[2] = Wg0; pp.src[3] = Wg1; pp.src[4] = Wg2; pp.src[5] = Wg3;
    pp.src[6] = Wb0; pp.src[7] = Wb1; pp.src[8] = Wb2; pp.src[9] = Wb3;
    k_prep<<<dim3(256, 10), 256>>>(pp);

    CtxP cp;
    cp.t = t; cp.cond = cond;
    cp.bg[0] = bg0; cp.bg[1] = bg1; cp.bg[2] = bg2; cp.bg[3] = bg3;
    k_ctx<<<dim3(128, 4), 256>>>(cp);

    k_zero<<<(Bsz * Ssz + 255) / 256, 256>>>(condg, Bsz * Ssz);

    cudaFuncSetAttribute(k_main, cudaFuncAttributeMaxDynamicSharedMemorySize, SMEM_BYTES);
    MainP mp;
    mp.z = z;
    mp.W0 = W0; mp.b0 = b0; mp.Wg0 = Wg0; mp.Wb0 = Wb0;
    mp.b1 = b1; mp.Wg1 = Wg1; mp.Wb1 = Wb1;
    mp.b2 = b2; mp.Wg2 = Wg2; mp.Wb2 = Wb2;
    mp.W3 = W3; mp.b3 = b3; mp.Wg3 = Wg3; mp.Wb3 = Wb3;
    mp.zdot = zdot; mp.tr = trace;
    k_main<<<dim3(Ssz / TOK, Bsz), 256, SMEM_BYTES>>>(mp);
}

// round 5
// speedup vs baseline: 1.0649x; 1.0649x over previous
#include <cuda_runtime.h>
#include <math.h>

#define Bsz 2048
#define Ssz 128
#define HID 256
#define DCc 130
#define TOK 32
#define THR 512
#define HSTR 260   // padded H row stride (floats): phases of 8 lanes hit 8 distinct 16B groups
#define CH 16      // k-rows per staged W chunk
#define NCH (HID / CH)          // 16 chunks per layer
#define WSF (CH * HID)          // floats per W buffer (4096)

// ---------------- device scratch (static, no allocation) ----------------
__device__ float g_Wt[2][HID * HID];      // W1, W2 transposed to K-major [k][o]
__device__ float g_WgT[4][DCc * HID];     // Wg_l transposed [c][o]
__device__ float g_WbT[4][DCc * HID];     // Wb_l transposed [c][o]
__device__ float g_cg[4][Bsz * HID];      // cond·Wg[:,2:] + bg + t*Wg[:,1]
__device__ float g_cb[4][Bsz * HID];      // cond·Wb[:,2:]      + t*Wb[:,1]

// ---------------- helpers ----------------
__device__ __forceinline__ float sigm(float x) {
    float e = expf(-fabsf(x));
    float s = 1.0f / (1.0f + e);
    return (x >= 0.0f) ? s : e / (1.0f + e);
}
__device__ __forceinline__ float splus(float x) {
    return fmaxf(x, 0.0f) + log1pf(expf(-fabsf(x)));
}
__device__ __forceinline__ unsigned long long pk2(float lo, float hi) {
    unsigned long long r;
    asm("mov.b64 %0, {%1, %2};" : "=l"(r) : "f"(lo), "f"(hi));
    return r;
}
__device__ __forceinline__ void up2(unsigned long long v, float& lo, float& hi) {
    asm("mov.b64 {%0, %1}, %2;" : "=f"(lo), "=f"(hi) : "l"(v));
}
__device__ __forceinline__ void fma2(unsigned long long& acc, unsigned long long a, unsigned long long b) {
    asm("fma.rn.f32x2 %0, %1, %2, %0;" : "+l"(acc) : "l"(a), "l"(b));
}
__device__ __forceinline__ float f4e(const float4& v, int i) {
    return (i == 0) ? v.x : (i == 1) ? v.y : (i == 2) ? v.z : v.w;
}

#define CPA_COMMIT asm volatile("cp.async.commit_group;")
#define CPA_WAIT2  asm volatile("cp.async.wait_group 2;")
#define CPA_WAIT1  asm volatile("cp.async.wait_group 1;")
#define CPA_WAIT0  asm volatile("cp.async.wait_group 0;")

// stage one CH x HID chunk of W (16KB = 1024 float4) into smem via cp.async.
// THR=512 threads -> each thread copies TWO float4 (tid and tid+512).
__device__ __forceinline__ void stageW(float* dst, const float* gsrc, int tid) {
    unsigned sa = (unsigned)__cvta_generic_to_shared((float4*)dst + tid);
    const float4* g = (const float4*)gsrc + tid;
    asm volatile("cp.async.cg.shared.global [%0], [%1], 16;" :: "r"(sa), "l"(g));
    asm volatile("cp.async.cg.shared.global [%0], [%1], 16;"
                 :: "r"(sa + THR * 16), "l"(g + THR));
}

// ---------------- prep: transposes ----------------
struct PrepP { const float* src[10]; };

__global__ void k_prep(PrepP p) {
    int id = blockIdx.y;
    int rows, cols;
    float* dst;
    switch (id) {
        case 0: rows = HID; cols = HID; dst = g_Wt[0]; break;
        case 1: rows = HID; cols = HID; dst = g_Wt[1]; break;
        case 2: rows = HID; cols = DCc; dst = g_WgT[0]; break;
        case 3: rows = HID; cols = DCc; dst = g_WgT[1]; break;
        case 4: rows = HID; cols = DCc; dst = g_WgT[2]; break;
        case 5: rows = 2;   cols = DCc; dst = g_WgT[3]; break;
        case 6: rows = HID; cols = DCc; dst = g_WbT[0]; break;
        case 7: rows = HID; cols = DCc; dst = g_WbT[1]; break;
        case 8: rows = HID; cols = DCc; dst = g_WbT[2]; break;
        default: rows = 2;  cols = DCc; dst = g_WbT[3]; break;
    }
    int idx = blockIdx.x * blockDim.x + threadIdx.x;
    if (idx < rows * cols) {
        int r = idx / cols, c = idx % cols;
        dst[c * rows + r] = p.src[id][idx];
    }
}

// ---------------- ctx: per-(l,b,o) gate / hyper-bias bases ----------------
struct CtxP { const float* t; const float* cond; const float* bg[4]; };

__global__ void k_ctx(CtxP p) {
    __shared__ float sc[16 * 128];
    int l = blockIdx.y;
    int b0 = blockIdx.x * 16;
    int tid = threadIdx.x;
    for (int i = tid; i < 16 * 128; i += 256) sc[i] = p.cond[b0 * 128 + i];
    __syncthreads();

    int dout = (l < 3) ? HID : 2;
    int o = tid;
    if (o < dout) {
        const float* wgT = g_WgT[l];
        const float* wbT = g_WbT[l];
        float ag[16], ab[16];
#pragma unroll
        for (int bb = 0; bb < 16; bb++) { ag[bb] = 0.f; ab[bb] = 0.f; }
        for (int c = 0; c < 128; c++) {
            float wg = wgT[(2 + c) * dout + o];
            float wb = wbT[(2 + c) * dout + o];
#pragma unroll
            for (int bb = 0; bb < 16; bb++) {
                float cv = sc[bb * 128 + c];
                ag[bb] = fmaf(cv, wg, ag[bb]);
                ab[bb] = fmaf(cv, wb, ab[bb]);
            }
        }
        float tv = __ldg(p.t);
        float baseg = __ldg(&p.bg[l][o]) + tv * wgT[1 * dout + o];
        float baseb = tv * wbT[1 * dout + o];
#pragma unroll
        for (int bb = 0; bb < 16; bb++) {
            g_cg[l][(b0 + bb) * HID + o] = ag[bb] + baseg;
            g_cb[l][(b0 + bb) * HID + o] = ab[bb] + baseb;
        }
    }
}

// ---------------- zero-fill for the condition-gradient output ----------------
__global__ void k_zero(float* dst, int n) {
    int idx = blockIdx.x * blockDim.x + threadIdx.x;
    if (idx < n) dst[idx] = 0.0f;
}

// ---------------- main fused kernel ----------------
struct MainP {
    const float* z;
    const float* W0; const float* b0; const float* Wg0; const float* Wb0;
    const float* b1; const float* Wg1; const float* Wb1;
    const float* b2; const float* Wg2; const float* Wb2;
    const float* W3; const float* b3; const float* Wg3; const float* Wb3;
    float* zdot; float* tr;
};

// dynamic smem layout (floats):
//   H    : 3*TOK*HSTR        = 24960
//   WS   : 4 * WSF (ring)    = 16384
//   sCg,sCb,sWg0,sWb0,sB     = 1280
//   sz(64) spos(32) sTr(64)  = 160
#define SMEM_FLOATS (3 * TOK * HSTR + 4 * WSF + 1280 + 160)
#define SMEM_BYTES  (SMEM_FLOATS * 4)

__global__ void __launch_bounds__(THR, 1) k_main(MainP p) {
    extern __shared__ float sm[];
    float* H    = sm;
    float* WS   = H + 3 * TOK * HSTR;
    float* sCg  = WS + 4 * WSF;
    float* sCb  = sCg + 256;
    float* sWg0 = sCb + 256;
    float* sWb0 = sWg0 + 256;
    float* sB   = sWb0 + 256;
    float* sz   = sB + 256;
    float* spos = sz + 64;
    float* sTr  = spos + 32;

    const int tid = threadIdx.x;
    const int b   = blockIdx.y;
    const int s0  = blockIdx.x * TOK;
    const int rt  = tid & 31;   // token row owned by this thread
    const int ct  = tid >> 5;   // column group 0..15 (whole warp shares ct -> W broadcast)

    if (tid < 64) sz[tid] = p.z[(b * Ssz + s0) * 2 + tid];
    if (tid < 32) spos[tid] = (float)(s0 + tid + 1) * (1.0f / Ssz);
    __syncthreads();

    // ---- layer 0: din=2 -> 256; thread (o = tid&255) handles 16 of 32 tokens ----
    {
        int o  = tid & 255;
        int t0 = (tid >> 8) * 16;
        float w00 = __ldg(&p.W0[o * 2 + 0]);
        float w01 = __ldg(&p.W0[o * 2 + 1]);
        float bb  = __ldg(&p.b0[o]);
        float cg  = g_cg[0][b * HID + o];
        float cb  = g_cb[0][b * HID + o];
        float wg0 = __ldg(&p.Wg0[o * DCc]);
        float wb0 = __ldg(&p.Wb0[o * DCc]);
#pragma unroll
        for (int i = 0; i < 16; i++) {
            int tk = t0 + i;
            float z0 = sz[2 * tk], z1 = sz[2 * tk + 1], pos = spos[tk];
            float g   = sigm(cg + pos * wg0);
            float lin = fmaf(z0, w00, fmaf(z1, w01, bb));
            float pre = fmaf(lin, g, cb + pos * wb0);
            float f   = sigm(pre) * g;
            H[(0 * TOK + tk) * HSTR + o] = splus(pre);
            H[(1 * TOK + tk) * HSTR + o] = f * w00;
            H[(2 * TOK + tk) * HSTR + o] = f * w01;
        }
    }
    // no sync needed here: first chunk-loop barrier below covers H visibility

    // ---- mid layers 1, 2: fused GEMM with cp.async 4-deep W ring ----
    for (int l = 1; l <= 2; l++) {
        const float* bl  = (l == 1) ? p.b1  : p.b2;
        const float* Wgl = (l == 1) ? p.Wg1 : p.Wg2;
        const float* Wbl = (l == 1) ? p.Wb1 : p.Wb2;
        const float* Wt  = g_Wt[l - 1];

        if (tid < 256) {
            sCg[tid]  = g_cg[l][b * HID + tid];
            sCb[tid]  = g_cb[l][b * HID + tid];
            sWg0[tid] = __ldg(&Wgl[tid * DCc]);
            sWb0[tid] = __ldg(&Wbl[tid * DCc]);
            sB[tid]   = __ldg(&bl[tid]);
        }

        unsigned long long acc[3][4][2];
#pragma unroll
        for (int v = 0; v < 3; v++)
#pragma unroll
            for (int j = 0; j < 4; j++) { acc[v][j][0] = 0ull; acc[v][j][1] = 0ull; }

        // prologue: prefetch chunks 0, 1
        stageW(WS + 0 * WSF, Wt + 0 * WSF, tid); CPA_COMMIT;
        stageW(WS + 1 * WSF, Wt + 1 * WSF, tid); CPA_COMMIT;

        for (int c = 0; c < NCH; c++) {
            if (c + 2 < NCH) {
                stageW(WS + ((c + 2) & 3) * WSF, Wt + (c + 2) * WSF, tid);
                CPA_COMMIT;
                CPA_WAIT2;
            } else if (c + 1 < NCH) {
                CPA_WAIT1;
            } else {
                CPA_WAIT0;
            }
            __syncthreads();   // chunk c visible to all; buf (c+2)&3 safe to overwrite

            const float* WB = WS + (c & 3) * WSF;
            const int kc = c * CH;
#pragma unroll
            for (int q = 0; q < CH / 4; q++) {
                int k = kc + q * 4;
                float4 a0 = *(const float4*)&H[(0 * TOK + rt) * HSTR + k];
                float4 a1 = *(const float4*)&H[(1 * TOK + rt) * HSTR + k];
                float4 a2 = *(const float4*)&H[(2 * TOK + rt) * HSTR + k];
#pragma unroll
                for (int ki = 0; ki < 4; ki++) {
                    float e0 = f4e(a0, ki), e1 = f4e(a1, ki), e2 = f4e(a2, ki);
                    unsigned long long A0 = pk2(e0, e0);
                    unsigned long long A1 = pk2(e1, e1);
                    unsigned long long A2 = pk2(e2, e2);
                    const float* wrow = WB + (q * 4 + ki) * HID + ct * 4;
#pragma unroll
                    for (int j = 0; j < 4; j++) {
                        float4 w = *(const float4*)(wrow + 64 * j);
                        unsigned long long W01 = pk2(w.x, w.y);
                        unsigned long long W23 = pk2(w.z, w.w);
                        fma2(acc[0][j][0], A0, W01); fma2(acc[0][j][1], A0, W23);
                        fma2(acc[1][j][0], A1, W01); fma2(acc[1][j][1], A1, W23);
                        fma2(acc[2][j][0], A2, W01); fma2(acc[2][j][1], A2, W23);
                    }
                }
            }
        }
        __syncthreads();   // all compute reads of H done before epilogue rewrites H

        // epilogue: gate + softplus + tangent scaling, write back to H
        {
            float pos = spos[rt];
            float fArr[16];
#pragma unroll
            for (int j = 0; j < 4; j++) {
                int c0 = ct * 4 + 64 * j;
                float a[4];
                up2(acc[0][j][0], a[0], a[1]);
                up2(acc[0][j][1], a[2], a[3]);
                float4 hv;
#pragma unroll
                for (int e = 0; e < 4; e++) {
                    int c = c0 + e;
                    float g   = sigm(sCg[c] + pos * sWg0[c]);
                    float pre = fmaf(a[e] + sB[c], g, sCb[c] + pos * sWb0[c]);
                    ((float*)&hv)[e] = splus(pre);
                    fArr[j * 4 + e] = sigm(pre) * g;
                }
                *(float4*)&H[(0 * TOK + rt) * HSTR + c0] = hv;
            }
#pragma unroll
            for (int v = 1; v < 3; v++) {
#pragma unroll
                for (int j = 0; j < 4; j++) {
                    int c0 = ct * 4 + 64 * j;
                    float a[4];
                    up2(acc[v][j][0], a[0], a[1]);
                    up2(acc[v][j][1], a[2], a[3]);
                    float4 dv;
#pragma unroll
                    for (int e = 0; e < 4; e++)
                        ((float*)&dv)[e] = fArr[j * 4 + e] * a[e];
                    *(float4*)&H[(v * TOK + rt) * HSTR + c0] = dv;
                }
            }
        }
        __syncthreads();
    }

    // ---- layer 3: 256 -> 2, only diagonal tangent dots needed ----
    if (tid < 128) {
        int tk = tid >> 2, r = tid & 3;
        int vec = (r < 2) ? 0 : (r - 1);
        int j   = (r < 2) ? r : (r - 2);
        const float* hrow = &H[(vec * TOK + tk) * HSTR];
        const float* w3   = p.W3 + j * HID;
        float accv = 0.0f;
#pragma unroll 8
        for (int k = 0; k < HID; k += 4) {
            float4 hv = *(const float4*)&hrow[k];
            float4 wv = *(const float4*)&w3[k];
            accv += hv.x * wv.x + hv.y * wv.y + hv.z * wv.z + hv.w * wv.w;
        }
        float pos = spos[tk];
        float g3 = sigm(g_cg[3][b * HID + j] + pos * __ldg(&p.Wg3[j * DCc]));
        if (vec == 0) {
            float hb3  = g_cb[3][b * HID + j] + pos * __ldg(&p.Wb3[j * DCc]);
            float outv = fmaf(accv + __ldg(&p.b3[j]), g3, hb3);
            p.zdot[(b * Ssz + s0 + tk) * 2 + j] = outv;
        } else {
            sTr[tk * 2 + j] = g3 * accv;
        }
    }
    __syncthreads();
    if (tid < TOK) p.tr[b * Ssz + s0 + tid] = -(sTr[tid * 2] + sTr[tid * 2 + 1]);
}

// ---------------- launch ----------------
extern "C" void kernel_launch(void* const* d_in, const int* in_sizes, int n_in,
                              void* d_out, int out_size) {
    const float* t    = (const float*)d_in[0];
    const float* z    = (const float*)d_in[1];
    const float* cond = (const float*)d_in[2];
    const float* W0  = (const float*)d_in[3];
    const float* b0  = (const float*)d_in[4];
    const float* Wg0 = (const float*)d_in[5];
    const float* bg0 = (const float*)d_in[6];
    const float* Wb0 = (const float*)d_in[7];
    const float* W1  = (const float*)d_in[8];
    const float* b1  = (const float*)d_in[9];
    const float* Wg1 = (const float*)d_in[10];
    const float* bg1 = (const float*)d_in[11];
    const float* Wb1 = (const float*)d_in[12];
    const float* W2  = (const float*)d_in[13];
    const float* b2  = (const float*)d_in[14];
    const float* Wg2 = (const float*)d_in[15];
    const float* bg2 = (const float*)d_in[16];
    const float* Wb2 = (const float*)d_in[17];
    const float* W3  = (const float*)d_in[18];
    const float* b3  = (const float*)d_in[19];
    const float* Wg3 = (const float*)d_in[20];
    const float* bg3 = (const float*)d_in[21];
    const float* Wb3 = (const float*)d_in[22];

    float* out = (float*)d_out;
    float* zdot    = out;                         // [2048,128,2]
    float* trace   = out + Bsz * Ssz * 2;         // [2048,128]
    float* condg   = out + Bsz * Ssz * 3;         // [2048,128] zeros

    PrepP pp;
    pp.src[0] = W1;  pp.src[1] = W2;
    pp.src[2] = Wg0; pp.src[3] = Wg1; pp.src[4] = Wg2; pp.src[5] = Wg3;
    pp.src[6] = Wb0; pp.src[7] = Wb1; pp.src[8] = Wb2; pp.src[9] = Wb3;
    k_prep<<<dim3(256, 10), 256>>>(pp);

    CtxP cp;
    cp.t = t; cp.cond = cond;
    cp.bg[0] = bg0; cp.bg[1] = bg1; cp.bg[2] = bg2; cp.bg[3] = bg3;
    k_ctx<<<dim3(128, 4), 256>>>(cp);

    k_zero<<<(Bsz * Ssz + 255) / 256, 256>>>(condg, Bsz * Ssz);

    cudaFuncSetAttribute(k_main, cudaFuncAttributeMaxDynamicSharedMemorySize, SMEM_BYTES);
    MainP mp;
    mp.z = z;
    mp.W0 = W0; mp.b0 = b0; mp.Wg0 = Wg0; mp.Wb0 = Wb0;
    mp.b1 = b1; mp.Wg1 = Wg1; mp.Wb1 = Wb1;
    mp.b2 = b2; mp.Wg2 = Wg2; mp.Wb2 = Wb2;
    mp.W3 = W3; mp.b3 = b3; mp.Wg3 = Wg3; mp.Wb3 = Wb3;
    mp.zdot = zdot; mp.tr = trace;
    k_main<<<dim3(Ssz / TOK, Bsz), THR, SMEM_BYTES>>>(mp);
}